// round 4
// baseline (speedup 1.0000x reference)
#include <cuda_runtime.h>
#include <cstdint>

#define BB 16
#define NN 1024
#define HH 768
#define NEG_INF_F (-9000000000000000.0f)
#define SLOPE_F 0.2f

// ---- static device scratch (no allocations allowed) ----
__device__ uint32_t g_mask[(size_t)BB * NN * 32];   // adjacency bitmask, 2 MB
__device__ __align__(16) float g_u1[HH], g_u2[HH];
__device__ float g_s1[BB * NN], g_s2[BB * NN];

// ---------------------------------------------------------------------------
// prep_mask: adj (fp32 0/1) -> per-row bitmask (adj > 1e-6)
// one block per row, 256 threads, float4 reads
// ---------------------------------------------------------------------------
__global__ void prep_mask_kernel(const float* __restrict__ adj) {
    __shared__ unsigned char s_nib[256];
    const int row = blockIdx.x;
    const int t = threadIdx.x;
    const float4 v = ((const float4*)(adj + (size_t)row * NN))[t];
    unsigned nib = (v.x > 1e-6f ? 1u : 0u) | (v.y > 1e-6f ? 2u : 0u) |
                   (v.z > 1e-6f ? 4u : 0u) | (v.w > 1e-6f ? 8u : 0u);
    s_nib[t] = (unsigned char)nib;
    __syncthreads();
    if (t < 32) {
        uint32_t w = 0;
#pragma unroll
        for (int i = 0; i < 8; ++i) w |= ((uint32_t)s_nib[t * 8 + i]) << (4 * i);
        g_mask[(size_t)row * 32 + t] = w;
    }
}

// ---------------------------------------------------------------------------
// u1 = W @ a[:H], u2 = W @ a[H:]
// ---------------------------------------------------------------------------
__global__ void compute_u_kernel(const float* __restrict__ W, const float* __restrict__ a) {
    int g = blockIdx.x * blockDim.x + threadIdx.x;
    if (g >= HH) return;
    const float* wr = W + (size_t)g * HH;
    float u1 = 0.f, u2 = 0.f;
#pragma unroll 8
    for (int f = 0; f < HH; ++f) {
        float w = wr[f];
        u1 += w * a[f];
        u2 += w * a[HH + f];
    }
    g_u1[g] = u1;
    g_u2[g] = u2;
}

// ---------------------------------------------------------------------------
// gather: nv[b, i0:i0+128, h0:h0+256] = sum_{j in mask(i)} x[b, j, h0:h0+256]
// x staged through double-buffered SMEM j-tiles (64 rows x 256 cols fp32,
// 64 KB per buffer) via cp.async; per-row ffs walk of the bitmask; register
// accumulators (warp owns 8 rows, lane owns float4s {lane, lane+32}).
// ---------------------------------------------------------------------------
#define MTILE 128
#define HCH 256
#define JT 64
#define NJT (NN / JT)                 // 16
#define TILE_F4 (JT * HCH / 4)        // 4096 float4 per buffer
#define GATHER_SMEM (2 * JT * HCH * 4)  // 131072 bytes

__device__ __forceinline__ void cp_async16(uint32_t dst, const void* src) {
    asm volatile("cp.async.cg.shared.global [%0], [%1], 16;" :: "r"(dst), "l"(src) : "memory");
}
__device__ __forceinline__ uint32_t smem_u32(const void* p) {
    uint32_t a;
    asm("{ .reg .u64 t; cvta.to.shared.u64 t, %1; cvt.u32.u64 %0, t; }" : "=r"(a) : "l"(p));
    return a;
}

__device__ __forceinline__ void load_tile(uint32_t s_f4_base, const float* __restrict__ x,
                                          int b, int jt, int h0) {
    // tile = 64 rows x 64 float4; 512 threads -> 8 float4 each
    const float* src0 = x + ((size_t)b * NN + (size_t)jt * JT) * HH + h0;
    const int t = threadIdx.x;
#pragma unroll
    for (int i = 0; i < 8; ++i) {
        int f = t + i * 512;          // 0..4095
        int r = f >> 6;
        int c4 = f & 63;
        cp_async16(s_f4_base + (uint32_t)f * 16u, src0 + (size_t)r * HH + c4 * 4);
    }
    asm volatile("cp.async.commit_group;" ::: "memory");
}

__global__ void __launch_bounds__(512, 1) gather_kernel(const float* __restrict__ x,
                                                        float* __restrict__ nv) {
    extern __shared__ __align__(16) float xs[];     // [2][64][256]
    const uint32_t s_base = smem_u32(xs);

    const int mt = blockIdx.x;        // 0..7
    const int hc = blockIdx.y;        // 0..2
    const int b  = blockIdx.z;        // 0..15
    const int i0 = mt * MTILE;
    const int h0 = hc * HCH;

    const int wid = threadIdx.x >> 5;
    const int lane = threadIdx.x & 31;
    const int r0 = wid * 8;           // warp's first row within tile

    float4 accA[8], accB[8];
#pragma unroll
    for (int r = 0; r < 8; ++r) {
        accA[r] = make_float4(0.f, 0.f, 0.f, 0.f);
        accB[r] = make_float4(0.f, 0.f, 0.f, 0.f);
    }

    // mask rows for this warp's 8 rows
    const uint32_t* mbase = g_mask + ((size_t)(b * NN + i0 + r0)) * 32;

    // prologue: tile 0 -> buffer 0
    load_tile(s_base, x, b, 0, h0);

    const float4* xs4 = (const float4*)xs;

    for (int jt = 0; jt < NJT; ++jt) {
        const int buf = jt & 1;
        if (jt + 1 < NJT) {
            load_tile(s_base + (uint32_t)(1 - buf) * (TILE_F4 * 16u), x, b, jt + 1, h0);
            asm volatile("cp.async.wait_group 1;" ::: "memory");
        } else {
            asm volatile("cp.async.wait_group 0;" ::: "memory");
        }
        __syncthreads();

        const float4* tb = xs4 + buf * TILE_F4;
        const int w0 = jt * 2;        // word index of this 64-bit window
#pragma unroll
        for (int r = 0; r < 8; ++r) {
            const uint32_t* mr = mbase + (size_t)r * 32 + w0;
            uint64_t m = (uint64_t)mr[0] | ((uint64_t)mr[1] << 32);
            float4 a = accA[r], bb4 = accB[r];
            while (m) {
                int j = __ffsll((long long)m) - 1;
                m &= m - 1;
                float4 va = tb[(j << 6) + lane];
                float4 vb = tb[(j << 6) + lane + 32];
                a.x += va.x; a.y += va.y; a.z += va.z; a.w += va.w;
                bb4.x += vb.x; bb4.y += vb.y; bb4.z += vb.z; bb4.w += vb.w;
            }
            accA[r] = a; accB[r] = bb4;
        }
        __syncthreads();   // all warps done with buf before it is overwritten
    }

    // writeout
#pragma unroll
    for (int r = 0; r < 8; ++r) {
        const int gi = i0 + r0 + r;
        float4* dst = (float4*)(nv + ((size_t)(b * NN + gi)) * HH + h0);
        dst[lane] = accA[r];
        dst[lane + 32] = accB[r];
    }
}

// ---------------------------------------------------------------------------
// s1/s2: one warp per row
// ---------------------------------------------------------------------------
__global__ void compute_s_kernel(const float* __restrict__ nv) {
    const int row = blockIdx.x * 8 + (threadIdx.x >> 5);
    const int lane = threadIdx.x & 31;
    const float4* r = (const float4*)(nv + (size_t)row * HH);
    const float4* u1 = (const float4*)g_u1;
    const float4* u2 = (const float4*)g_u2;
    float d1 = 0.f, d2 = 0.f;
#pragma unroll
    for (int k = lane; k < HH / 4; k += 32) {
        float4 v = r[k], w1 = u1[k], w2 = u2[k];
        d1 += v.x * w1.x + v.y * w1.y + v.z * w1.z + v.w * w1.w;
        d2 += v.x * w2.x + v.y * w2.y + v.z * w2.z + v.w * w2.w;
    }
#pragma unroll
    for (int o = 16; o > 0; o >>= 1) {
        d1 += __shfl_down_sync(0xffffffffu, d1, o);
        d2 += __shfl_down_sync(0xffffffffu, d2, o);
    }
    if (lane == 0) { g_s1[row] = d1; g_s2[row] = d2; }
}

// ---------------------------------------------------------------------------
// softmax: bitmask-driven, register-resident scores
// ---------------------------------------------------------------------------
__global__ void softmax_kernel(const float* __restrict__ nl, float* __restrict__ attn) {
    __shared__ float red[8];
    __shared__ float bc;
    const int row = blockIdx.x;
    const int b = row >> 10;
    const int tid = threadIdx.x;

    const float s1i = g_s1[row];
    const bool rv = nl[row] > 1e-6f;
    const uint32_t* mrow = g_mask + (size_t)row * 32;
    const float* nlb = nl + (size_t)b * NN;
    const float* s2b = g_s2 + (size_t)b * NN;

    float sc[4];
    float lmax = NEG_INF_F;
#pragma unroll
    for (int k = 0; k < 4; ++k) {
        const int j = tid + 256 * k;
        const uint32_t w = mrow[j >> 5];
        const bool v = (((w >> (j & 31)) & 1u) != 0u) && rv && (nlb[j] > 1e-6f);
        const float z = s1i + s2b[j];
        const float e = (z > 0.f) ? z : SLOPE_F * z;
        sc[k] = v ? e : NEG_INF_F;
        lmax = fmaxf(lmax, sc[k]);
    }
#pragma unroll
    for (int o = 16; o > 0; o >>= 1)
        lmax = fmaxf(lmax, __shfl_xor_sync(0xffffffffu, lmax, o));
    if ((tid & 31) == 0) red[tid >> 5] = lmax;
    __syncthreads();
    if (tid == 0) {
        float m = red[0];
#pragma unroll
        for (int k = 1; k < 8; ++k) m = fmaxf(m, red[k]);
        bc = m;
    }
    __syncthreads();
    const float m = bc;

    float lsum = 0.f;
#pragma unroll
    for (int k = 0; k < 4; ++k) {
        const float e = __expf(sc[k] - m);
        sc[k] = e;
        lsum += e;
    }
#pragma unroll
    for (int o = 16; o > 0; o >>= 1)
        lsum += __shfl_xor_sync(0xffffffffu, lsum, o);
    if ((tid & 31) == 0) red[tid >> 5] = lsum;
    __syncthreads();
    if (tid == 0) {
        float s = 0.f;
#pragma unroll
        for (int k = 0; k < 8; ++k) s += red[k];
        bc = 1.0f / s;
    }
    __syncthreads();
    const float inv = bc;

    float* orow = attn + (size_t)row * NN;
#pragma unroll
    for (int k = 0; k < 4; ++k)
        orow[tid + 256 * k] = sc[k] * inv;
}

// ---------------------------------------------------------------------------
extern "C" void kernel_launch(void* const* d_in, const int* in_sizes, int n_in,
                              void* d_out, int out_size) {
    const float* x   = (const float*)d_in[0];   // (B, N, H)
    const float* nl  = (const float*)d_in[1];   // (B, N)
    const float* adj = (const float*)d_in[2];   // (B, N, N)
    const float* W   = (const float*)d_in[3];   // (H, H)
    const float* a   = (const float*)d_in[4];   // (2H, 1)

    float* nv   = (float*)d_out;
    float* attn = nv + (size_t)BB * NN * HH;

    static int smem_set = 0;
    if (!smem_set) {
        cudaFuncSetAttribute(gather_kernel, cudaFuncAttributeMaxDynamicSharedMemorySize, GATHER_SMEM);
        smem_set = 1;
    }

    prep_mask_kernel<<<BB * NN, 256>>>(adj);
    compute_u_kernel<<<3, 256>>>(W, a);
    gather_kernel<<<dim3(NN / MTILE, HH / HCH, BB), 512, GATHER_SMEM>>>(x, nv);
    compute_s_kernel<<<(BB * NN) / 8, 256>>>(nv);
    softmax_kernel<<<BB * NN, 256>>>(nl, attn);
}